// round 3
// baseline (speedup 1.0000x reference)
#include <cuda_runtime.h>
#include <math.h>

#define C_DIM 1024
#define NQ 10            // gated queries (ref has NQ+1 = 11 query rows)
#define MAXN 100000
#define K1_RPW 3         // rows per warp per tile in pass 1
#define K1_WARPS 8
#define K1_RPB (K1_RPW * K1_WARPS)   // 24 rows per tile
#define K1_GRID 296                  // persistent blocks (2/SM)
#define K2_TILE 128
#define K2_GRID 592                  // persistent blocks (4/SM)

typedef unsigned long long u64;

// ---- scratch (static device memory; no allocations) ----
__device__ float g_Qd[NQ * C_DIM];                    // Qn[q] - Qn[NQ]
__device__ float g_logits[(size_t)NQ * MAXN];         // [q][n], 4 MB
__device__ float g_bmax[(size_t)K1_GRID * NQ];        // per-block max partials
__device__ float g_M[NQ];                             // per-q max logit
__device__ float g_Z[NQ];                             // per-q softmax denom
__device__ float g_partial[(size_t)K2_GRID * C_DIM];  // pass-2 partials
__device__ float g_pooled[C_DIM];

// packed 2xfp32 FMA
__device__ __forceinline__ u64 f2fma(u64 a, u64 b, u64 c) {
    u64 d;
    asm("fma.rn.f32x2 %0, %1, %2, %3;" : "=l"(d) : "l"(a), "l"(b), "l"(c));
    return d;
}
__device__ __forceinline__ float f2sum(u64 v) {
    return __uint_as_float((unsigned)v) + __uint_as_float((unsigned)(v >> 32));
}

// ============================================================
// K0: normalize Q rows, build Qd = Qn[q]-Qn[NQ]; init Z/pooled
// ============================================================
__global__ void k0_prep(const float* __restrict__ Q) {
    __shared__ float s_norm[NQ + 1];
    __shared__ float s_red[128];
    int t = threadIdx.x;
    for (int q = 0; q < NQ + 1; q++) {
        float ss = 0.f;
        for (int c = t; c < C_DIM; c += 128) {
            float v = Q[q * C_DIM + c];
            ss = fmaf(v, v, ss);
        }
        s_red[t] = ss;
        __syncthreads();
        for (int s = 64; s > 0; s >>= 1) {
            if (t < s) s_red[t] += s_red[t + s];
            __syncthreads();
        }
        if (t == 0) s_norm[q] = fmaxf(sqrtf(s_red[0]), 1e-12f);
        __syncthreads();
    }
    float invL = 1.0f / s_norm[NQ];
    for (int q = 0; q < NQ; q++) {
        float invq = 1.0f / s_norm[q];
        for (int c = t; c < C_DIM; c += 128)
            g_Qd[q * C_DIM + c] = Q[q * C_DIM + c] * invq - Q[NQ * C_DIM + c] * invL;
    }
    if (t < NQ) g_Z[t] = 0.f;
    for (int c = t; c < C_DIM; c += 128) g_pooled[c] = 0.f;
}

// ============================================================
// K1: logits[q][n] = 100 * (Qd[q] . X[n]) / max(||X[n]||, eps)
// persistent blocks; warp handles 3 rows/tile; packed f32x2 FMA
// ============================================================
__global__ __launch_bounds__(256, 2) void k1_logits(const float* __restrict__ X,
                                                    int N, int ntiles) {
    __shared__ float s_qd[NQ * C_DIM];          // 40 KB
    __shared__ float s_l[NQ][K1_RPB];
    __shared__ float s_wmax[K1_WARPS][NQ];
    int t = threadIdx.x;
    int warp = t >> 5, lane = t & 31;
    for (int i = t; i < NQ * C_DIM; i += 256) s_qd[i] = g_Qd[i];
    __syncthreads();

    float wmax[NQ];
#pragma unroll
    for (int q = 0; q < NQ; q++) wmax[q] = -1e30f;

    for (int tile = blockIdx.x; tile < ntiles; tile += gridDim.x) {
        int row0 = tile * K1_RPB + warp * K1_RPW;

        u64 acc[K1_RPW][NQ];
        u64 nacc[K1_RPW];
#pragma unroll
        for (int j = 0; j < K1_RPW; j++) {
            nacc[j] = 0ull;
#pragma unroll
            for (int q = 0; q < NQ; q++) acc[j][q] = 0ull;
        }

        const float* xp[K1_RPW];
#pragma unroll
        for (int j = 0; j < K1_RPW; j++) {
            int r = row0 + j;
            if (r >= N) r = N - 1;
            xp[j] = X + (size_t)r * C_DIM;
        }

#pragma unroll
        for (int kk = 0; kk < 8; kk++) {
            int cb = kk * 128 + lane * 4;
            ulonglong2 xv[K1_RPW];
#pragma unroll
            for (int j = 0; j < K1_RPW; j++)
                xv[j] = __ldcs((const ulonglong2*)(xp[j] + cb));
#pragma unroll
            for (int j = 0; j < K1_RPW; j++) {
                nacc[j] = f2fma(xv[j].x, xv[j].x, nacc[j]);
                nacc[j] = f2fma(xv[j].y, xv[j].y, nacc[j]);
            }
#pragma unroll
            for (int q = 0; q < NQ; q++) {
                ulonglong2 qv = *(const ulonglong2*)&s_qd[q * C_DIM + cb];
#pragma unroll
                for (int j = 0; j < K1_RPW; j++) {
                    acc[j][q] = f2fma(xv[j].x, qv.x, acc[j][q]);
                    acc[j][q] = f2fma(xv[j].y, qv.y, acc[j][q]);
                }
            }
        }

        // lane reduction + scale + stage
#pragma unroll
        for (int j = 0; j < K1_RPW; j++) {
            float ns = f2sum(nacc[j]);
            float dot[NQ];
#pragma unroll
            for (int q = 0; q < NQ; q++) dot[q] = f2sum(acc[j][q]);
#pragma unroll
            for (int off = 16; off; off >>= 1) {
                ns += __shfl_xor_sync(0xffffffffu, ns, off);
#pragma unroll
                for (int q = 0; q < NQ; q++)
                    dot[q] += __shfl_xor_sync(0xffffffffu, dot[q], off);
            }
            if (lane == 0) {
                int slot = warp * K1_RPW + j;
                if (row0 + j < N) {
                    float sc = 100.0f / fmaxf(sqrtf(ns), 1e-12f);
#pragma unroll
                    for (int q = 0; q < NQ; q++) {
                        float lv = dot[q] * sc;
                        s_l[q][slot] = lv;
                        wmax[q] = fmaxf(wmax[q], lv);
                    }
                } else {
#pragma unroll
                    for (int q = 0; q < NQ; q++) s_l[q][slot] = -1e30f;
                }
            }
        }
        __syncthreads();

        // coalesced logit store
        int col0 = tile * K1_RPB;
        for (int i = t; i < NQ * K1_RPB; i += 256) {
            int q = i / K1_RPB, c = i % K1_RPB;
            int n = col0 + c;
            if (n < N) g_logits[(size_t)q * N + n] = s_l[q][c];
        }
        __syncthreads();   // protect s_l before next tile overwrites
    }

    // block max: warp partials -> smem -> thread<NQ reduce
    if (lane == 0)
#pragma unroll
        for (int q = 0; q < NQ; q++) s_wmax[warp][q] = wmax[q];
    __syncthreads();
    if (t < NQ) {
        float m = -1e30f;
#pragma unroll
        for (int w = 0; w < K1_WARPS; w++) m = fmaxf(m, s_wmax[w][t]);
        g_bmax[(size_t)blockIdx.x * NQ + t] = m;
    }
}

// ============================================================
// K1m: merge per-block maxes -> g_M  (1 block, warp per q)
// ============================================================
__global__ void k1_merge(int nblocks) {
    int q = threadIdx.x >> 5, lane = threadIdx.x & 31;
    if (q >= NQ) return;
    float m = -1e30f;
    for (int b = lane; b < nblocks; b += 32)
        m = fmaxf(m, g_bmax[(size_t)b * NQ + q]);
#pragma unroll
    for (int off = 16; off; off >>= 1)
        m = fmaxf(m, __shfl_xor_sync(0xffffffffu, m, off));
    if (lane == 0) g_M[q] = m;
}

// ============================================================
// K1.5b: Z[q] = sum_n exp(l - M)   (grid = NQ*16 blocks)
// ============================================================
__global__ void k15b_z(int N) {
    int q = blockIdx.x >> 4, part = blockIdx.x & 15;
    const float* l = g_logits + (size_t)q * N;
    float M = g_M[q];
    float s = 0.f;
    int n4 = N >> 2;
    int stride = 16 * 256;
    int i = part * 256 + threadIdx.x;
    for (; i + stride < n4; i += 2 * stride) {
        float4 v0 = *(const float4*)(l + 4 * i);
        float4 v1 = *(const float4*)(l + 4 * (i + stride));
        s += __expf(v0.x - M) + __expf(v0.y - M) + __expf(v0.z - M) + __expf(v0.w - M);
        s += __expf(v1.x - M) + __expf(v1.y - M) + __expf(v1.z - M) + __expf(v1.w - M);
    }
    for (; i < n4; i += stride) {
        float4 v = *(const float4*)(l + 4 * i);
        s += __expf(v.x - M) + __expf(v.y - M) + __expf(v.z - M) + __expf(v.w - M);
    }
    for (int n = 4 * n4 + part * 256 + threadIdx.x; n < N; n += stride)
        s += __expf(l[n] - M);
    __shared__ float red[256];
    int t = threadIdx.x;
    red[t] = s;
    __syncthreads();
    for (int st = 128; st > 0; st >>= 1) {
        if (t < st) red[t] += red[t + st];
        __syncthreads();
    }
    if (t == 0) atomicAdd(&g_Z[q], red[0]);
}

// ============================================================
// K2: persistent; acc[c] += g[n]*X[n][c] over block's tiles
//     g[n] = (1/NQ) * sum_q exp(l[q][n]-M_q)/Z_q
// ============================================================
__global__ __launch_bounds__(256) void k2_wsum(const float* __restrict__ X,
                                               int N, int ntiles) {
    __shared__ float s_g[K2_TILE];
    __shared__ float s_m[NQ], s_iz[NQ];
    int t = threadIdx.x;
    if (t < NQ) { s_m[t] = g_M[t]; s_iz[t] = (1.0f / NQ) / g_Z[t]; }
    __syncthreads();

    float4 a = make_float4(0.f, 0.f, 0.f, 0.f);

    for (int tile = blockIdx.x; tile < ntiles; tile += gridDim.x) {
        int n0 = tile * K2_TILE;
        int nv = min(K2_TILE, N - n0);
        __syncthreads();   // previous tile's s_g reads complete
        if (t < K2_TILE) {
            float gs = 0.f;
            if (t < nv) {
                int n = n0 + t;
#pragma unroll
                for (int q = 0; q < NQ; q++)
                    gs = fmaf(__expf(g_logits[(size_t)q * N + n] - s_m[q]), s_iz[q], gs);
            }
            s_g[t] = gs;
        }
        __syncthreads();

        const float* xb = X + (size_t)n0 * C_DIM + 4 * t;
        int r = 0;
        for (; r + 8 <= nv; r += 8) {
            float4 x[8];
#pragma unroll
            for (int i = 0; i < 8; i++)
                x[i] = __ldcs((const float4*)(xb + (size_t)(r + i) * C_DIM));
#pragma unroll
            for (int i = 0; i < 8; i++) {
                float g = s_g[r + i];
                a.x = fmaf(g, x[i].x, a.x); a.y = fmaf(g, x[i].y, a.y);
                a.z = fmaf(g, x[i].z, a.z); a.w = fmaf(g, x[i].w, a.w);
            }
        }
        for (; r < nv; r++) {
            float4 x = __ldcs((const float4*)(xb + (size_t)r * C_DIM));
            float g = s_g[r];
            a.x = fmaf(g, x.x, a.x); a.y = fmaf(g, x.y, a.y);
            a.z = fmaf(g, x.z, a.z); a.w = fmaf(g, x.w, a.w);
        }
    }
    *(float4*)(g_partial + (size_t)blockIdx.x * C_DIM + 4 * t) = a;
}

// ============================================================
// K2.5: pooled[c] = sum_b partial[b][c]   (grid 64 x 128)
// ============================================================
__global__ void k25_reduce(int nblocks) {
    int cpart = blockIdx.x & 7;
    int bpart = blockIdx.x >> 3;
    int c = cpart * 128 + threadIdx.x;
    float s = 0.f;
    for (int bb = bpart; bb < nblocks; bb += 8)
        s += g_partial[(size_t)bb * C_DIM + c];
    atomicAdd(&g_pooled[c], s);
}

// ============================================================
// K3: out[j] = b[j] + sum_c pooled[c]*W[j][c]   (grid 128 x 256)
// ============================================================
__global__ __launch_bounds__(256) void k3_linear(const float* __restrict__ W,
                                                 const float* __restrict__ bias,
                                                 float* __restrict__ out) {
    int t = threadIdx.x;
    int j0 = blockIdx.x * 8;
    float4 p = *(const float4*)(g_pooled + 4 * t);
    float part[8];
#pragma unroll
    for (int j = 0; j < 8; j++) {
        const float4 w = *(const float4*)(W + (size_t)(j0 + j) * C_DIM + 4 * t);
        part[j] = fmaf(p.x, w.x, fmaf(p.y, w.y, fmaf(p.z, w.z, p.w * w.w)));
    }
#pragma unroll
    for (int j = 0; j < 8; j++)
#pragma unroll
        for (int off = 16; off; off >>= 1)
            part[j] += __shfl_xor_sync(0xffffffffu, part[j], off);
    __shared__ float s_p[8][8];
    int warp = t >> 5, lane = t & 31;
    if (lane == 0)
#pragma unroll
        for (int j = 0; j < 8; j++) s_p[warp][j] = part[j];
    __syncthreads();
    if (t < 8) {
        float s = 0.f;
#pragma unroll
        for (int w = 0; w < 8; w++) s += s_p[w][t];
        out[j0 + t] = s + bias[j0 + t];
    }
}

// ============================================================
extern "C" void kernel_launch(void* const* d_in, const int* in_sizes, int n_in,
                              void* d_out, int out_size) {
    const float* X = (const float*)d_in[0];
    const float* Q = (const float*)d_in[1];
    const float* W = (const float*)d_in[2];
    const float* b = (const float*)d_in[3];
    float* out = (float*)d_out;

    int N = in_sizes[0] / C_DIM;
    if (N > MAXN) N = MAXN;

    int k1_tiles = (N + K1_RPB - 1) / K1_RPB;
    int k2_tiles = (N + K2_TILE - 1) / K2_TILE;
    int k1_grid = min(K1_GRID, k1_tiles);
    int k2_grid = min(K2_GRID, k2_tiles);

    k0_prep<<<1, 128>>>(Q);
    k1_logits<<<k1_grid, 256>>>(X, N, k1_tiles);
    k1_merge<<<1, NQ * 32>>>(k1_grid);
    k15b_z<<<NQ * 16, 256>>>(N);
    k2_wsum<<<k2_grid, 256>>>(X, N, k2_tiles);
    k25_reduce<<<64, 128>>>(k2_grid);
    k3_linear<<<128, 256>>>(W, b, out);
}

// round 4
// speedup vs baseline: 1.3017x; 1.3017x over previous
#include <cuda_runtime.h>
#include <math.h>

#define C_DIM 1024
#define NQ 10            // gated queries (ref has NQ+1 = 11 query rows)
#define MAXN 100000
#define K1_RPW 4         // rows per warp per tile in pass 1
#define K1_WARPS 8
#define K1_RPB (K1_RPW * K1_WARPS)   // 32 rows per tile
#define K1_GRID 148                  // persistent blocks (1/SM, 8 warps)
#define K2_TILE 128
#define K2_GRID 592                  // persistent blocks (4/SM)

typedef unsigned long long u64;

// ---- scratch (static device memory; no allocations) ----
__device__ float g_Qd[NQ * C_DIM];                    // Qn[q] - Qn[NQ]
__device__ float g_logits[(size_t)NQ * MAXN];         // [q][n], 4 MB
__device__ float g_bmax[(size_t)K1_GRID * NQ];        // per-block max partials
__device__ float g_M[NQ];                             // per-q max logit
__device__ float g_Z[NQ];                             // per-q softmax denom
__device__ float g_partial[(size_t)K2_GRID * C_DIM];  // pass-2 partials
__device__ float g_pooled[C_DIM];

// packed 2xfp32 FMA
__device__ __forceinline__ u64 f2fma(u64 a, u64 b, u64 c) {
    u64 d;
    asm("fma.rn.f32x2 %0, %1, %2, %3;" : "=l"(d) : "l"(a), "l"(b), "l"(c));
    return d;
}
__device__ __forceinline__ float f2sum(u64 v) {
    return __uint_as_float((unsigned)v) + __uint_as_float((unsigned)(v >> 32));
}

// ============================================================
// K0: normalize Q rows, build Qd = Qn[q]-Qn[NQ]; init Z/pooled
// ============================================================
__global__ void k0_prep(const float* __restrict__ Q) {
    __shared__ float s_norm[NQ + 1];
    __shared__ float s_red[128];
    int t = threadIdx.x;
    for (int q = 0; q < NQ + 1; q++) {
        float ss = 0.f;
        for (int c = t; c < C_DIM; c += 128) {
            float v = Q[q * C_DIM + c];
            ss = fmaf(v, v, ss);
        }
        s_red[t] = ss;
        __syncthreads();
        for (int s = 64; s > 0; s >>= 1) {
            if (t < s) s_red[t] += s_red[t + s];
            __syncthreads();
        }
        if (t == 0) s_norm[q] = fmaxf(sqrtf(s_red[0]), 1e-12f);
        __syncthreads();
    }
    float invL = 1.0f / s_norm[NQ];
    for (int q = 0; q < NQ; q++) {
        float invq = 1.0f / s_norm[q];
        for (int c = t; c < C_DIM; c += 128)
            g_Qd[q * C_DIM + c] = Q[q * C_DIM + c] * invq - Q[NQ * C_DIM + c] * invL;
    }
    if (t < NQ) g_Z[t] = 0.f;
    for (int c = t; c < C_DIM; c += 128) g_pooled[c] = 0.f;
}

// ============================================================
// K1: logits[q][n] = 100 * (Qd[q] . X[n]) / max(||X[n]||, eps)
// persistent 148 blocks, 1 CTA/SM, full register budget (no spill),
// warp = 4 rows/tile, double-buffered X prefetch, packed f32x2 FMA
// ============================================================
__global__ __launch_bounds__(256, 1) void k1_logits(const float* __restrict__ X,
                                                    int N, int ntiles) {
    __shared__ float s_qd[NQ * C_DIM];          // 40 KB
    __shared__ float s_l[NQ][K1_RPB];
    __shared__ float s_wmax[K1_WARPS][NQ];
    int t = threadIdx.x;
    int warp = t >> 5, lane = t & 31;
    for (int i = t; i < NQ * C_DIM; i += 256) s_qd[i] = g_Qd[i];
    __syncthreads();

    float wmax[NQ];
#pragma unroll
    for (int q = 0; q < NQ; q++) wmax[q] = -1e30f;

    for (int tile = blockIdx.x; tile < ntiles; tile += gridDim.x) {
        int row0 = tile * K1_RPB + warp * K1_RPW;

        u64 acc[K1_RPW][NQ];
        u64 nacc[K1_RPW];
#pragma unroll
        for (int j = 0; j < K1_RPW; j++) {
            nacc[j] = 0ull;
#pragma unroll
            for (int q = 0; q < NQ; q++) acc[j][q] = 0ull;
        }

        const float* xp[K1_RPW];
#pragma unroll
        for (int j = 0; j < K1_RPW; j++) {
            int r = row0 + j;
            if (r >= N) r = N - 1;
            xp[j] = X + (size_t)r * C_DIM;
        }

        ulonglong2 xa[K1_RPW], xb[K1_RPW];
#pragma unroll
        for (int j = 0; j < K1_RPW; j++)
            xa[j] = __ldcs((const ulonglong2*)(xp[j] + lane * 4));

#pragma unroll
        for (int kk = 0; kk < 8; kk++) {
            // prefetch next chunk
            if (kk < 7) {
                int cbn = (kk + 1) * 128 + lane * 4;
                if (kk & 1) {
#pragma unroll
                    for (int j = 0; j < K1_RPW; j++)
                        xa[j] = __ldcs((const ulonglong2*)(xp[j] + cbn));
                } else {
#pragma unroll
                    for (int j = 0; j < K1_RPW; j++)
                        xb[j] = __ldcs((const ulonglong2*)(xp[j] + cbn));
                }
            }
            ulonglong2* xv = (kk & 1) ? xb : xa;
            int cb = kk * 128 + lane * 4;
#pragma unroll
            for (int j = 0; j < K1_RPW; j++) {
                nacc[j] = f2fma(xv[j].x, xv[j].x, nacc[j]);
                nacc[j] = f2fma(xv[j].y, xv[j].y, nacc[j]);
            }
#pragma unroll
            for (int q = 0; q < NQ; q++) {
                ulonglong2 qv = *(const ulonglong2*)&s_qd[q * C_DIM + cb];
#pragma unroll
                for (int j = 0; j < K1_RPW; j++) {
                    acc[j][q] = f2fma(xv[j].x, qv.x, acc[j][q]);
                    acc[j][q] = f2fma(xv[j].y, qv.y, acc[j][q]);
                }
            }
        }

        // lane reduction + scale + stage
#pragma unroll
        for (int j = 0; j < K1_RPW; j++) {
            float ns = f2sum(nacc[j]);
            float dot[NQ];
#pragma unroll
            for (int q = 0; q < NQ; q++) dot[q] = f2sum(acc[j][q]);
#pragma unroll
            for (int off = 16; off; off >>= 1) {
                ns += __shfl_xor_sync(0xffffffffu, ns, off);
#pragma unroll
                for (int q = 0; q < NQ; q++)
                    dot[q] += __shfl_xor_sync(0xffffffffu, dot[q], off);
            }
            if (lane == 0) {
                int slot = warp * K1_RPW + j;
                if (row0 + j < N) {
                    float sc = 100.0f / fmaxf(sqrtf(ns), 1e-12f);
#pragma unroll
                    for (int q = 0; q < NQ; q++) {
                        float lv = dot[q] * sc;
                        s_l[q][slot] = lv;
                        wmax[q] = fmaxf(wmax[q], lv);
                    }
                } else {
#pragma unroll
                    for (int q = 0; q < NQ; q++) s_l[q][slot] = -1e30f;
                }
            }
        }
        __syncthreads();

        // coalesced logit store
        int col0 = tile * K1_RPB;
        for (int i = t; i < NQ * K1_RPB; i += 256) {
            int q = i >> 5, c = i & (K1_RPB - 1);
            int n = col0 + c;
            if (n < N) g_logits[(size_t)q * N + n] = s_l[q][c];
        }
        __syncthreads();   // protect s_l before next tile overwrites
    }

    // block max: warp partials -> smem -> thread<NQ reduce
    if (lane == 0)
#pragma unroll
        for (int q = 0; q < NQ; q++) s_wmax[warp][q] = wmax[q];
    __syncthreads();
    if (t < NQ) {
        float m = -1e30f;
#pragma unroll
        for (int w = 0; w < K1_WARPS; w++) m = fmaxf(m, s_wmax[w][t]);
        g_bmax[(size_t)blockIdx.x * NQ + t] = m;
    }
}

// ============================================================
// K1m: merge per-block maxes -> g_M  (1 block, warp per q)
// ============================================================
__global__ void k1_merge(int nblocks) {
    int q = threadIdx.x >> 5, lane = threadIdx.x & 31;
    if (q >= NQ) return;
    float m = -1e30f;
    for (int b = lane; b < nblocks; b += 32)
        m = fmaxf(m, g_bmax[(size_t)b * NQ + q]);
#pragma unroll
    for (int off = 16; off; off >>= 1)
        m = fmaxf(m, __shfl_xor_sync(0xffffffffu, m, off));
    if (lane == 0) g_M[q] = m;
}

// ============================================================
// K1.5b: Z[q] = sum_n exp(l - M)   (grid = NQ*32 blocks)
// ============================================================
__global__ void k15b_z(int N) {
    int q = blockIdx.x >> 5, part = blockIdx.x & 31;
    const float* l = g_logits + (size_t)q * N;
    float M = g_M[q];
    float s = 0.f;
    int n4 = N >> 2;
    int stride = 32 * 256;
    for (int i = part * 256 + threadIdx.x; i < n4; i += stride) {
        float4 v = *(const float4*)(l + 4 * i);
        s += __expf(v.x - M) + __expf(v.y - M) + __expf(v.z - M) + __expf(v.w - M);
    }
    for (int n = 4 * n4 + part * 256 + threadIdx.x; n < N; n += stride)
        s += __expf(l[n] - M);
    __shared__ float red[256];
    int t = threadIdx.x;
    red[t] = s;
    __syncthreads();
    for (int st = 128; st > 0; st >>= 1) {
        if (t < st) red[t] += red[t + st];
        __syncthreads();
    }
    if (t == 0) atomicAdd(&g_Z[q], red[0]);
}

// ============================================================
// K2: persistent; acc[c] += g[n]*X[n][c] over block's tiles
//     g[n] = (1/NQ) * sum_q exp(l[q][n]-M_q)/Z_q
// ============================================================
__global__ __launch_bounds__(256) void k2_wsum(const float* __restrict__ X,
                                               int N, int ntiles) {
    __shared__ float s_g[K2_TILE];
    __shared__ float s_m[NQ], s_iz[NQ];
    int t = threadIdx.x;
    if (t < NQ) { s_m[t] = g_M[t]; s_iz[t] = (1.0f / NQ) / g_Z[t]; }
    __syncthreads();

    float4 a = make_float4(0.f, 0.f, 0.f, 0.f);

    for (int tile = blockIdx.x; tile < ntiles; tile += gridDim.x) {
        int n0 = tile * K2_TILE;
        int nv = min(K2_TILE, N - n0);
        __syncthreads();   // previous tile's s_g reads complete
        if (t < K2_TILE) {
            float gs = 0.f;
            if (t < nv) {
                int n = n0 + t;
#pragma unroll
                for (int q = 0; q < NQ; q++)
                    gs = fmaf(__expf(g_logits[(size_t)q * N + n] - s_m[q]), s_iz[q], gs);
            }
            s_g[t] = gs;
        }
        __syncthreads();

        const float* xb = X + (size_t)n0 * C_DIM + 4 * t;
        int r = 0;
        for (; r + 8 <= nv; r += 8) {
            float4 x[8];
#pragma unroll
            for (int i = 0; i < 8; i++)
                x[i] = __ldcs((const float4*)(xb + (size_t)(r + i) * C_DIM));
#pragma unroll
            for (int i = 0; i < 8; i++) {
                float g = s_g[r + i];
                a.x = fmaf(g, x[i].x, a.x); a.y = fmaf(g, x[i].y, a.y);
                a.z = fmaf(g, x[i].z, a.z); a.w = fmaf(g, x[i].w, a.w);
            }
        }
        for (; r < nv; r++) {
            float4 x = __ldcs((const float4*)(xb + (size_t)r * C_DIM));
            float g = s_g[r];
            a.x = fmaf(g, x.x, a.x); a.y = fmaf(g, x.y, a.y);
            a.z = fmaf(g, x.z, a.z); a.w = fmaf(g, x.w, a.w);
        }
    }
    *(float4*)(g_partial + (size_t)blockIdx.x * C_DIM + 4 * t) = a;
}

// ============================================================
// K2.5: pooled[c] = sum_b partial[b][c]   (grid 64 x 128)
// ============================================================
__global__ void k25_reduce(int nblocks) {
    int cpart = blockIdx.x & 7;
    int bpart = blockIdx.x >> 3;
    int c = cpart * 128 + threadIdx.x;
    float s = 0.f;
    for (int bb = bpart; bb < nblocks; bb += 8)
        s += g_partial[(size_t)bb * C_DIM + c];
    atomicAdd(&g_pooled[c], s);
}

// ============================================================
// K3: out[j] = b[j] + sum_c pooled[c]*W[j][c]   (grid 128 x 256)
// ============================================================
__global__ __launch_bounds__(256) void k3_linear(const float* __restrict__ W,
                                                 const float* __restrict__ bias,
                                                 float* __restrict__ out) {
    int t = threadIdx.x;
    int j0 = blockIdx.x * 8;
    float4 p = *(const float4*)(g_pooled + 4 * t);
    float part[8];
#pragma unroll
    for (int j = 0; j < 8; j++) {
        const float4 w = *(const float4*)(W + (size_t)(j0 + j) * C_DIM + 4 * t);
        part[j] = fmaf(p.x, w.x, fmaf(p.y, w.y, fmaf(p.z, w.z, p.w * w.w)));
    }
#pragma unroll
    for (int j = 0; j < 8; j++)
#pragma unroll
        for (int off = 16; off; off >>= 1)
            part[j] += __shfl_xor_sync(0xffffffffu, part[j], off);
    __shared__ float s_p[8][8];
    int warp = t >> 5, lane = t & 31;
    if (lane == 0)
#pragma unroll
        for (int j = 0; j < 8; j++) s_p[warp][j] = part[j];
    __syncthreads();
    if (t < 8) {
        float s = 0.f;
#pragma unroll
        for (int w = 0; w < 8; w++) s += s_p[w][t];
        out[j0 + t] = s + bias[j0 + t];
    }
}

// ============================================================
extern "C" void kernel_launch(void* const* d_in, const int* in_sizes, int n_in,
                              void* d_out, int out_size) {
    const float* X = (const float*)d_in[0];
    const float* Q = (const float*)d_in[1];
    const float* W = (const float*)d_in[2];
    const float* b = (const float*)d_in[3];
    float* out = (float*)d_out;

    int N = in_sizes[0] / C_DIM;
    if (N > MAXN) N = MAXN;

    int k1_tiles = (N + K1_RPB - 1) / K1_RPB;
    int k2_tiles = (N + K2_TILE - 1) / K2_TILE;
    int k1_grid = (K1_GRID < k1_tiles) ? K1_GRID : k1_tiles;
    int k2_grid = (K2_GRID < k2_tiles) ? K2_GRID : k2_tiles;

    k0_prep<<<1, 128>>>(Q);
    k1_logits<<<k1_grid, 256>>>(X, N, k1_tiles);
    k1_merge<<<1, NQ * 32>>>(k1_grid);
    k15b_z<<<NQ * 32, 256>>>(N);
    k2_wsum<<<k2_grid, 256>>>(X, N, k2_tiles);
    k25_reduce<<<64, 128>>>(k2_grid);
    k3_linear<<<128, 256>>>(W, b, out);
}